// round 7
// baseline (speedup 1.0000x reference)
#include <cuda_runtime.h>
#include <cuda_fp16.h>
#include <cooperative_groups.h>

namespace cg = cooperative_groups;

#define N_NODES 50000
#define HALF_N  25000
#define N_EDGES 1600000
#define BATCH   4
#define T_STEPS 50
#define DT      0.02f

#define NBLK    148
#define NTHR    1024
#define ROWS_PER_BLK 338                     // ceil(50000/148)
#define GROUPS  (NTHR / 8)                   // 128 row-groups (8 lanes each)
#define NPASS   3                            // ceil(338/128)

// SMEM layout (dynamic)
#define SM_RATES_BYTES (HALF_N * 8)          // 200000 : fp16x4 per node (this CTA's half)
#define SM_ACC_OFF     SM_RATES_BYTES
#define SM_ACC_BYTES   (BATCH * ROWS_PER_BLK * 4)   // 5408
#define SM_STG_OFF     (SM_ACC_OFF + SM_ACC_BYTES)
#define SM_STG_BYTES   (ROWS_PER_BLK * BATCH * 2)   // 2704
#define SMEM_TOTAL     (SM_STG_OFF + SM_STG_BYTES)  // 208112

// ---------------- static scratch (no allocations allowed) ----------------
__device__ int    g_hist[N_NODES];
__device__ int    g_row_start[N_NODES + 1];
__device__ int    g_cursor[N_NODES];
__device__ int2   g_edges[N_EDGES];            // (src_col, weight bits), CSR by target
__device__ uint4  g_rates4[2][N_NODES / 2];    // ping-pong fp16x4 rates (8B/node)
__device__ float  g_alpha[N_NODES];
__device__ unsigned          g_bar_count;
__device__ volatile unsigned g_bar_sense;

// ---------------- preprocessing ----------------

__global__ void init_kernel(const float* __restrict__ bias,
                            const float* __restrict__ tau) {
    int n = blockIdx.x * blockDim.x + threadIdx.x;
    if (n == 0) { g_bar_count = 0; g_bar_sense = 0; }
    if (n >= N_NODES) return;
    g_hist[n] = 0;
    float b = bias[n];
    float r = fmaxf(b, 0.0f);
    unsigned hb = (unsigned)__half_as_ushort(__float2half_rn(r));
    unsigned u  = hb | (hb << 16);
    ((uint2*)g_rates4[0])[n] = make_uint2(u, u);
    float tt = fmaxf(tau[n], DT);
    g_alpha[n] = DT / tt;
}

__global__ void hist_kernel(const int* __restrict__ tgt) {
    int e = blockIdx.x * blockDim.x + threadIdx.x;
    if (e >= N_EDGES) return;
    atomicAdd(&g_hist[tgt[e]], 1);
}

__global__ void scan_kernel() {
    __shared__ int s[1024];
    int tid = threadIdx.x;
    const int chunk = (N_NODES + 1023) / 1024;
    int beg = tid * chunk;
    int end = min(beg + chunk, N_NODES);
    int sum = 0;
    for (int i = beg; i < end; i++) sum += g_hist[i];
    s[tid] = sum;
    __syncthreads();
    for (int off = 1; off < 1024; off <<= 1) {
        int v = (tid >= off) ? s[tid - off] : 0;
        __syncthreads();
        s[tid] += v;
        __syncthreads();
    }
    int prefix = (tid > 0) ? s[tid - 1] : 0;
    for (int i = beg; i < end; i++) {
        g_row_start[i] = prefix;
        g_cursor[i]    = prefix;
        prefix += g_hist[i];
    }
    if (tid == 0) g_row_start[N_NODES] = s[1023];
}

__global__ void scatter_kernel(const int*   __restrict__ src,
                               const int*   __restrict__ tgt,
                               const float* __restrict__ sign,
                               const float* __restrict__ cnt,
                               const float* __restrict__ str) {
    int e = blockIdx.x * blockDim.x + threadIdx.x;
    if (e >= N_EDGES) return;
    float w = sign[e] * fmaxf(cnt[e], 0.0f) * fmaxf(str[e], 0.0f);
    int pos = atomicAdd(&g_cursor[tgt[e]], 1);
    g_edges[pos] = make_int2(src[e], __float_as_int(w));
}

// ---------------- software grid barrier (all NBLK blocks resident) ------
__device__ __forceinline__ void grid_barrier(unsigned target) {
    __syncthreads();
    if (threadIdx.x == 0) {
        __threadfence();
        unsigned a = atomicAdd(&g_bar_count, 1);
        if (a == NBLK - 1) {
            g_bar_count = 0;
            __threadfence();
            g_bar_sense = target;
        } else {
            while (g_bar_sense != target) { }
            __threadfence();
        }
    }
    __syncthreads();
}

// ---------------- persistent cluster kernel: all 50 steps ----------------
// Cluster of 2 CTAs: rank r holds fp16x4 rates for nodes [r*25000,(r+1)*25000)
// in SMEM. Gathers are LDS (local half) / DSMEM (peer half) instead of random
// global LDG — removes the L1tex replay bottleneck (2.07 cyc/wavefront).
extern "C" __global__ void __launch_bounds__(NTHR, 1) __cluster_dims__(2, 1, 1)
persist_kernel(const float* __restrict__ x,
               float*       __restrict__ out,
               const float* __restrict__ bias) {
    extern __shared__ unsigned char smem_raw[];
    uint2*  s_rates = (uint2*)smem_raw;                       // [HALF_N]
    float*  s_acc   = (float*)(smem_raw + SM_ACC_OFF);        // [BATCH][ROWS_PER_BLK]
    __half* s_stg   = (__half*)(smem_raw + SM_STG_OFF);       // [ROWS_PER_BLK][BATCH]

    cg::cluster_group cluster = cg::this_cluster();
    unsigned rank = cluster.block_rank();
    uint2* peer = cluster.map_shared_rank(s_rates, rank ^ 1);
    const uint2* base0 = (rank == 0) ? s_rates : peer;   // nodes [0, 25000)
    const uint2* base1 = (rank == 0) ? peer : s_rates;   // nodes [25000, 50000)

    int tid = threadIdx.x;
    int sub = tid & 7;
    int grp = tid >> 3;
    int rowbase = blockIdx.x * ROWS_PER_BLK;
    int nrows   = min(ROWS_PER_BLK, N_NODES - rowbase);

    // epilogue thread state: each thread owns up to 2 (row,batch) slots,
    // slot = p*NTHR + tid; consecutive tid -> consecutive rows (coalesced x/out)
    int   er[2]  = {-1, -1};
    int   eb[2]  = {0, 0};
    float ev[2]  = {0.f, 0.f}, ea[2] = {0.f, 0.f}, ebi[2] = {0.f, 0.f};
#pragma unroll
    for (int p = 0; p < 2; p++) {
        int slot = p * NTHR + tid;
        if (slot < ROWS_PER_BLK * BATCH) {
            int b  = slot / ROWS_PER_BLK;
            int rl = slot % ROWS_PER_BLK;
            if (rl < nrows) {
                int row = rowbase + rl;
                er[p] = rl; eb[p] = b;
                ebi[p] = bias[row];
                ea[p]  = g_alpha[row];
                ev[p]  = ebi[p];                 // v0 = bias
            }
        }
    }

    // gather-phase row metadata (loaded once)
    int beg[NPASS], end[NPASS], rloc[NPASS];
#pragma unroll
    for (int p = 0; p < NPASS; p++) {
        int rl = p * GROUPS + grp;
        bool ok = rl < nrows;
        int row = rowbase + rl;
        beg[p]  = ok ? g_row_start[row]     : 0;
        end[p]  = ok ? g_row_start[row + 1] : 0;
        rloc[p] = ok ? rl : -1;
    }

    // initial fill of this CTA's half from buffer 0
    {
        const uint4* srcp = g_rates4[0] + (int)rank * (HALF_N / 2);
        uint4* dstp = (uint4*)s_rates;
        for (int i = tid; i < HALF_N / 2; i += NTHR) dstp[i] = srcp[i];
    }
    cluster.sync();

    for (int t = 0; t < T_STEPS; t++) {
        // ---- gather phase: SpMV rows from SMEM/DSMEM rates ----
#pragma unroll
        for (int p = 0; p < NPASS; p++) {
            float4 acc = make_float4(0.f, 0.f, 0.f, 0.f);
            for (int e0 = beg[p]; e0 < end[p]; e0 += 32) {
                int2 ed[4];
                bool pr[4];
#pragma unroll
                for (int j = 0; j < 4; j++) {
                    int ee = e0 + sub + 8 * j;
                    pr[j] = ee < end[p];
                    ed[j] = pr[j] ? g_edges[ee] : make_int2(0, 0);
                }
#pragma unroll
                for (int j = 0; j < 4; j++) {
                    if (pr[j]) {
                        int s = ed[j].x;
                        const uint2* rp = (s < HALF_N) ? (base0 + s)
                                                       : (base1 + (s - HALF_N));
                        uint2 rv = *rp;
                        float2 flo = __half22float2(*(const __half2*)&rv.x);
                        float2 fhi = __half22float2(*(const __half2*)&rv.y);
                        float w = __int_as_float(ed[j].y);
                        acc.x = fmaf(w, flo.x, acc.x);
                        acc.y = fmaf(w, flo.y, acc.y);
                        acc.z = fmaf(w, fhi.x, acc.z);
                        acc.w = fmaf(w, fhi.y, acc.w);
                    }
                }
            }
#pragma unroll
            for (int off = 4; off; off >>= 1) {
                acc.x += __shfl_down_sync(0xffffffffu, acc.x, off);
                acc.y += __shfl_down_sync(0xffffffffu, acc.y, off);
                acc.z += __shfl_down_sync(0xffffffffu, acc.z, off);
                acc.w += __shfl_down_sync(0xffffffffu, acc.w, off);
            }
            if (sub == 0 && rloc[p] >= 0) {
                s_acc[0 * ROWS_PER_BLK + rloc[p]] = acc.x;
                s_acc[1 * ROWS_PER_BLK + rloc[p]] = acc.y;
                s_acc[2 * ROWS_PER_BLK + rloc[p]] = acc.z;
                s_acc[3 * ROWS_PER_BLK + rloc[p]] = acc.w;
            }
        }
        __syncthreads();

        // ---- epilogue: Euler update, coalesced x/out, stage fp16 rate ----
#pragma unroll
        for (int p = 0; p < 2; p++) {
            if (er[p] >= 0) {
                int row = rowbase + er[p];
                int idx = (eb[p] * T_STEPS + t) * N_NODES + row;
                float sum = s_acc[eb[p] * ROWS_PER_BLK + er[p]];
                float v = ev[p];
                float vn = v + ea[p] * (ebi[p] + sum + x[idx] - v);
                ev[p] = vn;
                float rl = fmaxf(vn, 0.f);
                out[idx] = rl;
                s_stg[er[p] * BATCH + eb[p]] = __float2half_rn(rl);
            }
        }
        __syncthreads();

        if (t + 1 < T_STEPS) {
            // pack + publish new rates to ping-pong global buffer
            int wbuf = (t + 1) & 1;
            uint2* gout = (uint2*)g_rates4[wbuf];
            for (int rl = tid; rl < nrows; rl += NTHR) {
                uint2 packed = *(const uint2*)&s_stg[rl * BATCH];
                gout[rowbase + rl] = packed;
            }
            grid_barrier((unsigned)(t + 1));
            // refill SMEM half with the new rates
            const uint4* srcp = g_rates4[wbuf] + (int)rank * (HALF_N / 2);
            uint4* dstp = (uint4*)s_rates;
            for (int i = tid; i < HALF_N / 2; i += NTHR) dstp[i] = srcp[i];
            cluster.sync();
        }
    }

    // FIX (R5 crash): no CTA may exit while its cluster peer can still issue
    // DSMEM reads against our SMEM (last-step gather). Hold the cluster
    // together until both CTAs are fully done.
    cluster.sync();
}

// ---------------- launch ----------------
extern "C" void kernel_launch(void* const* d_in, const int* in_sizes, int n_in,
                              void* d_out, int out_size) {
    const float* x    = (const float*)d_in[0];
    const float* bias = (const float*)d_in[1];
    const float* tau  = (const float*)d_in[2];
    const float* sign = (const float*)d_in[3];
    const float* cnt  = (const float*)d_in[4];
    const float* str  = (const float*)d_in[5];
    const int*   src  = (const int*)  d_in[6];
    const int*   tgt  = (const int*)  d_in[7];
    float*       out  = (float*)d_out;

    // idempotent, no static guard (harness rule), not a stream op
    cudaFuncSetAttribute(persist_kernel,
                         cudaFuncAttributeMaxDynamicSharedMemorySize,
                         SMEM_TOTAL);

    init_kernel<<<(N_NODES + 255) / 256, 256>>>(bias, tau);
    hist_kernel<<<(N_EDGES + 255) / 256, 256>>>(tgt);
    scan_kernel<<<1, 1024>>>();
    scatter_kernel<<<(N_EDGES + 255) / 256, 256>>>(src, tgt, sign, cnt, str);

    persist_kernel<<<NBLK, NTHR, SMEM_TOTAL>>>(x, out, bias);
}